// round 6
// baseline (speedup 1.0000x reference)
#include <cuda_runtime.h>

// Problem constants (SUBDIVISIONS=7, BATCH=16)
#define BATCH 16
#define YDIM  640
#define XDIM  256
#define BH    128            // YDIM/5
#define YX    (YDIM*XDIM)    // 163840
#define NV    (YX + 2)       // 163842 vertices
#define BPT   2              // batches per thread in the fused loss kernel

// Scratch (static __device__ — no allocation allowed)
__device__ float4 g_v4[BATCH * NV];   // padded xyz_ per batch (~42 MB)
__device__ int    g_cnt[NV];          // per-vertex ring fill counters
__device__ int2   g_ring[NV * 6];     // per-vertex opposite-edge pairs (a,b)
__device__ int4   g_nbr[NV * 2];      // ring-ordered neighbors: [n0..n5, cnt, _]
__device__ double g_acc;              // fused loss accumulator
__device__ unsigned int g_done;       // ticket counter for fused finalization

// ---------------------------------------------------------------------------
// K0: tiny zero kernel (runs on the side stream ahead of k_ring)
// ---------------------------------------------------------------------------
__global__ void k_zero() {
    int i = blockIdx.x * blockDim.x + threadIdx.x;
    if (i < NV) g_cnt[i] = 0;
    if (i == 0) { g_acc = 0.0; g_done = 0u; }
}

// ---------------------------------------------------------------------------
// K1: build v = [grid verts ; top pole ; bottom pole] as float4 (w unused).
// inputs layout: (B, 3, Y, X) row-major
// ---------------------------------------------------------------------------
__global__ void k_build_v(const float* __restrict__ inp) {
    int vtx = blockIdx.x * blockDim.x + threadIdx.x;
    int b   = blockIdx.y;
    if (vtx > YX + 1) return;
    const float* base = inp + (size_t)b * 3 * YX;
    float4 o;
    o.w = 0.0f;
    if (vtx < YX) {
        o.x = base[vtx];
        o.y = base[YX + vtx];
        o.z = base[2 * YX + vtx];
    } else if (vtx == YX) {
        float s[3];
        #pragma unroll
        for (int c = 0; c < 3; c++) {
            s[c] = 0.0f;
            #pragma unroll
            for (int i = 0; i < 5; i++) s[c] += base[c * YX + (i * BH) * XDIM];
            s[c] *= 0.2f;
        }
        o.x = s[0]; o.y = s[1]; o.z = s[2];
    } else {
        float s[3];
        #pragma unroll
        for (int c = 0; c < 3; c++) {
            s[c] = 0.0f;
            #pragma unroll
            for (int i = 1; i <= 5; i++)
                s[c] += base[c * YX + (i * BH - 1) * XDIM + (XDIM - 1)];
            s[c] *= 0.2f;
        }
        o.x = s[0]; o.y = s[1]; o.z = s[2];
    }
    g_v4[(size_t)b * NV + vtx] = o;
}

// ---------------------------------------------------------------------------
// K2: collect per-vertex opposite-edge pairs from faces (batch-independent).
// Face (f0,f1,f2): pair (f1,f2)->f0, (f2,f0)->f1, (f0,f1)->f2.
// Identity: summing full face normals around a closed ring telescopes to
// vn[v] = sum_i a_i x b_i over opposite-edge pairs.
// ---------------------------------------------------------------------------
__global__ void k_ring(const int* __restrict__ faces, int F) {
    int f = blockIdx.x * blockDim.x + threadIdx.x;
    if (f >= F) return;
    int a = faces[3 * f], b = faces[3 * f + 1], c = faces[3 * f + 2];
    int s;
    s = atomicAdd(&g_cnt[a], 1); g_ring[a * 6 + s] = make_int2(b, c);
    s = atomicAdd(&g_cnt[b], 1); g_ring[b * 6 + s] = make_int2(c, a);
    s = atomicAdd(&g_cnt[c], 1); g_ring[c * 6 + s] = make_int2(a, b);
}

// ---------------------------------------------------------------------------
// K2b: chain pairs into cyclic ring order (succ(a)=b), packed into 2 int4s.
// vn[v] = sum_j n_j x n_{j+1 mod 6}; for deg-5 slot 5 duplicates n_0 so the
// wrap cross term vanishes. cnt doubles as the vertex degree.
// ---------------------------------------------------------------------------
__global__ void k_order() {
    int v = blockIdx.x * blockDim.x + threadIdx.x;
    if (v >= NV) return;
    int cnt = g_cnt[v];
    int2 pr[6];
    #pragma unroll
    for (int i = 0; i < 6; i++)
        pr[i] = (i < cnt) ? g_ring[v * 6 + i] : make_int2(-1, -1);
    int ord[6];
    ord[0] = pr[0].x;
    int cur = pr[0].y;
    #pragma unroll
    for (int k = 1; k < 6; k++) {
        ord[k] = cur;
        int nxt = cur;
        #pragma unroll
        for (int i = 0; i < 6; i++)
            if (pr[i].x == cur) nxt = pr[i].y;
        cur = nxt;
    }
    if (cnt == 5) ord[5] = ord[0];
    g_nbr[2 * v]     = make_int4(ord[0], ord[1], ord[2], ord[3]);
    g_nbr[2 * v + 1] = make_int4(ord[4], ord[5], cnt, 0);
}

// ---------------------------------------------------------------------------
// K3: fused loss. One thread per vertex, BPT batches per thread.
// 7 LDG.128 gathers + 9 coalesced target reads per vertex-batch.
// Last block (ticket) writes the final scalar.
// ---------------------------------------------------------------------------
__global__ void __launch_bounds__(256) k_loss(const float* __restrict__ target,
                                             float* __restrict__ out,
                                             unsigned int nblocks) {
    int vtx = blockIdx.x * blockDim.x + threadIdx.x;
    float local = 0.0f;
    if (vtx < NV) {
        int4 lo = g_nbr[2 * vtx];
        int4 hi = g_nbr[2 * vtx + 1];
        int n[6] = {lo.x, lo.y, lo.z, lo.w, hi.x, hi.y};
        int cnt  = hi.z;
        float invd = 1.0f / (float)cnt;
        const float inv3 = 1.0f / 3.0f;

        #pragma unroll
        for (int bb = 0; bb < BPT; bb++) {
            int b = blockIdx.y * BPT + bb;
            const float4* vb = g_v4 + (size_t)b * NV;

            float4 p[6];
            #pragma unroll
            for (int i = 0; i < 6; i++) p[i] = __ldg(vb + n[i]);
            float4 pv = __ldg(vb + vtx);

            // ring-ordered cross sum: vn = sum_j p_j x p_{(j+1)%6}
            float nx = 0.f, ny = 0.f, nz = 0.f;
            #pragma unroll
            for (int j = 0; j < 6; j++) {
                const float4 a = p[j];
                const float4 c = p[(j + 1) % 6];
                nx += a.y * c.z - a.z * c.y;
                ny += a.z * c.x - a.x * c.z;
                nz += a.x * c.y - a.y * c.x;
            }
            // neighbor sum (subtract the duplicated n0 if deg==5)
            float sx = 0.f, sy = 0.f, sz = 0.f;
            #pragma unroll
            for (int j = 0; j < 6; j++) { sx += p[j].x; sy += p[j].y; sz += p[j].z; }
            if (cnt == 5) { sx -= p[0].x; sy -= p[0].y; sz -= p[0].z; }

            const float* t = target + (size_t)b * 9 * NV + vtx;
            // position loss
            float dx = pv.x - t[0];
            float dy = pv.y - t[(size_t)NV];
            float dz = pv.z - t[2 * (size_t)NV];
            float lpos = dx * dx + dy * dy + dz * dz;
            // normal cosine loss
            float nn  = sqrtf(nx * nx + ny * ny + nz * nz);
            float inv = 1.0f / fmaxf(nn, 1e-12f);
            float ux = nx * inv, uy = ny * inv, uz = nz * inv;
            float un = sqrtf(ux * ux + uy * uy + uz * uz);
            float tx = t[3 * (size_t)NV], ty = t[4 * (size_t)NV], tz = t[5 * (size_t)NV];
            float tn = sqrtf(tx * tx + ty * ty + tz * tz);
            float cosv = (ux * tx + uy * ty + uz * tz) / fmaxf(un * tn, 1e-8f);
            // Laplacian loss
            float dlx = (pv.x - sx * invd) - t[6 * (size_t)NV];
            float dly = (pv.y - sy * invd) - t[7 * (size_t)NV];
            float dlz = (pv.z - sz * invd) - t[8 * (size_t)NV];
            float llap = dlx * dlx + dly * dly + dlz * dlz;

            local += (lpos + llap) * inv3 + (1.0f - cosv);
        }
    }

    // warp shuffle reduce, then cross-warp smem reduce, one atomic per block
    #pragma unroll
    for (int off = 16; off > 0; off >>= 1)
        local += __shfl_xor_sync(0xFFFFFFFFu, local, off);
    __shared__ float shw[8];
    int wid = threadIdx.x >> 5;
    if ((threadIdx.x & 31) == 0) shw[wid] = local;
    __syncthreads();
    if (threadIdx.x == 0) {
        float s = 0.f;
        #pragma unroll
        for (int i = 0; i < 8; i++) s += shw[i];
        atomicAdd(&g_acc, (double)s);
        __threadfence();
        unsigned int ticket = atomicAdd(&g_done, 1u);
        if (ticket == nblocks - 1u) {
            out[0] = (float)(g_acc / ((double)BATCH * (double)NV));
        }
    }
}

extern "C" void kernel_launch(void* const* d_in, const int* in_sizes, int n_in,
                              void* d_out, int out_size) {
    const float* inputs = (const float*)d_in[0];
    const float* target = (const float*)d_in[1];
    const int*   faces  = (const int*)  d_in[2];
    int F = in_sizes[2] / 3;

    // Side stream + events for fork-join overlap of the topology chain
    // (zero -> ring -> order) with k_build_v. Created once on first call
    // (the correctness run), reused by the captured graph thereafter.
    static cudaStream_t s_side = nullptr;
    static cudaEvent_t  s_fork = nullptr, s_join = nullptr;
    if (s_side == nullptr) {
        cudaStreamCreateWithFlags(&s_side, cudaStreamNonBlocking);
        cudaEventCreateWithFlags(&s_fork, cudaEventDisableTiming);
        cudaEventCreateWithFlags(&s_join, cudaEventDisableTiming);
    }

    cudaStream_t main_s = 0;  // harness captures the legacy/default stream

    dim3 blk256(256);

    // fork
    cudaEventRecord(s_fork, main_s);
    cudaStreamWaitEvent(s_side, s_fork, 0);

    // side stream: topology chain (independent of vertex positions)
    k_zero <<<(NV + 255) / 256, blk256, 0, s_side>>>();
    k_ring <<<(F + 255) / 256, blk256, 0, s_side>>>(faces, F);
    k_order<<<(NV + 255) / 256, blk256, 0, s_side>>>();
    cudaEventRecord(s_join, s_side);

    // main stream: vertex build, concurrent with the side chain
    k_build_v<<<dim3((YX + 2 + 255) / 256, BATCH), blk256, 0, main_s>>>(inputs);

    // join, then fused loss
    cudaStreamWaitEvent(main_s, s_join, 0);
    dim3 lgrid((NV + 255) / 256, BATCH / BPT);
    unsigned int nblocks = lgrid.x * lgrid.y;
    k_loss<<<lgrid, blk256, 0, main_s>>>(target, (float*)d_out, nblocks);
}

// round 7
// speedup vs baseline: 1.0747x; 1.0747x over previous
#include <cuda_runtime.h>

// Problem constants (SUBDIVISIONS=7, BATCH=16)
#define BATCH 16
#define YDIM  640
#define XDIM  256
#define BH    128            // YDIM/5
#define YX    (YDIM*XDIM)    // 163840
#define NV    (YX + 2)       // 163842 vertices
#define BPT   4              // batches per thread in the fused loss kernel

// Scratch (static __device__ — no allocation allowed)
__device__ float4 g_v4[BATCH * NV];   // padded xyz_ per batch (~42 MB)
__device__ int    g_cnt[NV];          // per-vertex ring fill counters
__device__ int2   g_ring[NV * 6];     // per-vertex opposite-edge pairs (a,b)
__device__ int4   g_nbr[NV * 2];      // ring-ordered neighbors: [n0..n5, cnt, _]
__device__ double g_acc;              // fused loss accumulator
__device__ unsigned int g_done;       // ticket counter for fused finalization

// ---------------------------------------------------------------------------
// K1: build v = [grid verts ; top pole ; bottom pole] as float4 (w unused).
// Also zeroes g_cnt / g_acc / g_done in the b==0 slice.
// inputs layout: (B, 3, Y, X) row-major
// ---------------------------------------------------------------------------
__global__ void k_build_v(const float* __restrict__ inp) {
    int vtx = blockIdx.x * blockDim.x + threadIdx.x;
    int b   = blockIdx.y;
    if (vtx > YX + 1) return;
    if (b == 0) {
        g_cnt[vtx] = 0;
        if (vtx == 0) { g_acc = 0.0; g_done = 0u; }
    }
    const float* base = inp + (size_t)b * 3 * YX;
    float4 o;
    o.w = 0.0f;
    if (vtx < YX) {
        o.x = base[vtx];
        o.y = base[YX + vtx];
        o.z = base[2 * YX + vtx];
    } else if (vtx == YX) {
        float s[3];
        #pragma unroll
        for (int c = 0; c < 3; c++) {
            s[c] = 0.0f;
            #pragma unroll
            for (int i = 0; i < 5; i++) s[c] += base[c * YX + (i * BH) * XDIM];
            s[c] *= 0.2f;
        }
        o.x = s[0]; o.y = s[1]; o.z = s[2];
    } else {
        float s[3];
        #pragma unroll
        for (int c = 0; c < 3; c++) {
            s[c] = 0.0f;
            #pragma unroll
            for (int i = 1; i <= 5; i++)
                s[c] += base[c * YX + (i * BH - 1) * XDIM + (XDIM - 1)];
            s[c] *= 0.2f;
        }
        o.x = s[0]; o.y = s[1]; o.z = s[2];
    }
    g_v4[(size_t)b * NV + vtx] = o;
}

// ---------------------------------------------------------------------------
// K2: collect per-vertex opposite-edge pairs from faces (batch-independent).
// Face (f0,f1,f2): pair (f1,f2)->f0, (f2,f0)->f1, (f0,f1)->f2.
// Identity: summing full face normals around a closed ring telescopes to
// vn[v] = sum_i a_i x b_i over opposite-edge pairs.
// ---------------------------------------------------------------------------
__global__ void k_ring(const int* __restrict__ faces, int F) {
    int f = blockIdx.x * blockDim.x + threadIdx.x;
    if (f >= F) return;
    int a = faces[3 * f], b = faces[3 * f + 1], c = faces[3 * f + 2];
    int s;
    s = atomicAdd(&g_cnt[a], 1); g_ring[a * 6 + s] = make_int2(b, c);
    s = atomicAdd(&g_cnt[b], 1); g_ring[b * 6 + s] = make_int2(c, a);
    s = atomicAdd(&g_cnt[c], 1); g_ring[c * 6 + s] = make_int2(a, b);
}

// ---------------------------------------------------------------------------
// K2b: chain pairs into cyclic ring order (succ(a)=b), packed into 2 int4s.
// vn[v] = sum_j n_j x n_{j+1 mod 6}; for deg-5 slot 5 duplicates n_0 so the
// wrap cross term vanishes. cnt doubles as the vertex degree.
// ---------------------------------------------------------------------------
__global__ void k_order() {
    int v = blockIdx.x * blockDim.x + threadIdx.x;
    if (v >= NV) return;
    int cnt = g_cnt[v];
    int2 pr[6];
    #pragma unroll
    for (int i = 0; i < 6; i++)
        pr[i] = (i < cnt) ? g_ring[v * 6 + i] : make_int2(-1, -1);
    int ord[6];
    ord[0] = pr[0].x;
    int cur = pr[0].y;
    #pragma unroll
    for (int k = 1; k < 6; k++) {
        ord[k] = cur;
        int nxt = cur;
        #pragma unroll
        for (int i = 0; i < 6; i++)
            if (pr[i].x == cur) nxt = pr[i].y;
        cur = nxt;
    }
    if (cnt == 5) ord[5] = ord[0];
    g_nbr[2 * v]     = make_int4(ord[0], ord[1], ord[2], ord[3]);
    g_nbr[2 * v + 1] = make_int4(ord[4], ord[5], cnt, 0);
}

// ---------------------------------------------------------------------------
// K3: fused loss. One thread per vertex, BPT batches per thread.
// Incremental ring-cross accumulation: only first/prev/cur neighbor positions
// stay live, cutting register pressure so the (128,12) launch bound is met
// without spills -> higher occupancy for this latency-bound kernel.
// Last block (ticket) writes the final scalar.
// ---------------------------------------------------------------------------
__global__ void __launch_bounds__(128, 12)
k_loss(const float* __restrict__ target, float* __restrict__ out,
       unsigned int nblocks) {
    int vtx = blockIdx.x * blockDim.x + threadIdx.x;
    float local = 0.0f;
    if (vtx < NV) {
        int4 lo = g_nbr[2 * vtx];
        int4 hi = g_nbr[2 * vtx + 1];
        int n[6] = {lo.x, lo.y, lo.z, lo.w, hi.x, hi.y};
        int cnt  = hi.z;
        float invd = 1.0f / (float)cnt;
        const float inv3 = 1.0f / 3.0f;

        #pragma unroll
        for (int bb = 0; bb < BPT; bb++) {
            int b = blockIdx.y * BPT + bb;
            const float4* vb = g_v4 + (size_t)b * NV;

            float4 pv = __ldg(vb + vtx);

            // incremental ring cross-sum + neighbor sum:
            // vn = sum_j p_j x p_{j+1}, wrap term handled at the end.
            float4 pfirst = __ldg(vb + n[0]);
            float4 prev = pfirst;
            float sx = pfirst.x, sy = pfirst.y, sz = pfirst.z;
            float nx = 0.f, ny = 0.f, nz = 0.f;
            #pragma unroll
            for (int j = 1; j < 6; j++) {
                float4 c = __ldg(vb + n[j]);
                nx += prev.y * c.z - prev.z * c.y;
                ny += prev.z * c.x - prev.x * c.z;
                nz += prev.x * c.y - prev.y * c.x;
                sx += c.x; sy += c.y; sz += c.z;
                prev = c;
            }
            // wrap term p5 x p0 (zero when deg==5 since p5==p0)
            nx += prev.y * pfirst.z - prev.z * pfirst.y;
            ny += prev.z * pfirst.x - prev.x * pfirst.z;
            nz += prev.x * pfirst.y - prev.y * pfirst.x;
            if (cnt == 5) { sx -= pfirst.x; sy -= pfirst.y; sz -= pfirst.z; }

            const float* t = target + (size_t)b * 9 * NV + vtx;
            // position loss
            float dx = pv.x - t[0];
            float dy = pv.y - t[(size_t)NV];
            float dz = pv.z - t[2 * (size_t)NV];
            float lpos = dx * dx + dy * dy + dz * dz;
            // normal cosine loss
            float nn  = sqrtf(nx * nx + ny * ny + nz * nz);
            float inv = 1.0f / fmaxf(nn, 1e-12f);
            float ux = nx * inv, uy = ny * inv, uz = nz * inv;
            float un = sqrtf(ux * ux + uy * uy + uz * uz);
            float tx = t[3 * (size_t)NV], ty = t[4 * (size_t)NV], tz = t[5 * (size_t)NV];
            float tn = sqrtf(tx * tx + ty * ty + tz * tz);
            float cosv = (ux * tx + uy * ty + uz * tz) / fmaxf(un * tn, 1e-8f);
            // Laplacian loss
            float dlx = (pv.x - sx * invd) - t[6 * (size_t)NV];
            float dly = (pv.y - sy * invd) - t[7 * (size_t)NV];
            float dlz = (pv.z - sz * invd) - t[8 * (size_t)NV];
            float llap = dlx * dlx + dly * dly + dlz * dlz;

            local += (lpos + llap) * inv3 + (1.0f - cosv);
        }
    }

    // warp shuffle reduce, then cross-warp smem reduce, one atomic per block
    #pragma unroll
    for (int off = 16; off > 0; off >>= 1)
        local += __shfl_xor_sync(0xFFFFFFFFu, local, off);
    __shared__ float shw[4];
    int wid = threadIdx.x >> 5;
    if ((threadIdx.x & 31) == 0) shw[wid] = local;
    __syncthreads();
    if (threadIdx.x == 0) {
        float s = shw[0] + shw[1] + shw[2] + shw[3];
        atomicAdd(&g_acc, (double)s);
        __threadfence();
        unsigned int ticket = atomicAdd(&g_done, 1u);
        if (ticket == nblocks - 1u) {
            out[0] = (float)(g_acc / ((double)BATCH * (double)NV));
        }
    }
}

extern "C" void kernel_launch(void* const* d_in, const int* in_sizes, int n_in,
                              void* d_out, int out_size) {
    const float* inputs = (const float*)d_in[0];
    const float* target = (const float*)d_in[1];
    const int*   faces  = (const int*)  d_in[2];
    int F = in_sizes[2] / 3;

    dim3 blk256(256);
    k_build_v<<<dim3((YX + 2 + 255) / 256, BATCH), blk256>>>(inputs);
    k_ring   <<<(F + 255) / 256, blk256>>>(faces, F);
    k_order  <<<(NV + 255) / 256, blk256>>>();
    dim3 lgrid((NV + 127) / 128, BATCH / BPT);
    unsigned int nblocks = lgrid.x * lgrid.y;
    k_loss   <<<lgrid, 128>>>(target, (float*)d_out, nblocks);
}

// round 8
// speedup vs baseline: 1.1853x; 1.1030x over previous
#include <cuda_runtime.h>

// Problem constants (SUBDIVISIONS=7, BATCH=16)
#define BATCH 16
#define YDIM  640
#define XDIM  256
#define BH    128            // YDIM/5
#define YX    (YDIM*XDIM)    // 163840
#define NV    (YX + 2)       // 163842 vertices
#define BPT   4              // batches per thread in the fused loss kernel

// Scratch (static __device__ — no allocation allowed)
__device__ float4 g_v4[BATCH * NV];   // padded xyz_ per batch (~42 MB)
__device__ int    g_cnt[NV];          // per-vertex ring fill counters
__device__ int2   g_ring[NV * 6];     // per-vertex opposite-edge pairs (a,b)
__device__ int4   g_nbr[NV * 2];      // ring-ordered neighbors: [n0..n5, cnt, _]
__device__ double g_acc;              // fused loss accumulator
__device__ unsigned int g_done;       // ticket counter for fused finalization

// ---------------------------------------------------------------------------
// K1: build v = [grid verts ; top pole ; bottom pole] as float4 (w unused).
// Also zeroes g_cnt / g_acc / g_done in the b==0 slice.
// inputs layout: (B, 3, Y, X) row-major
// ---------------------------------------------------------------------------
__global__ void k_build_v(const float* __restrict__ inp) {
    int vtx = blockIdx.x * blockDim.x + threadIdx.x;
    int b   = blockIdx.y;
    if (vtx > YX + 1) return;
    if (b == 0) {
        g_cnt[vtx] = 0;
        if (vtx == 0) { g_acc = 0.0; g_done = 0u; }
    }
    const float* base = inp + (size_t)b * 3 * YX;
    float4 o;
    o.w = 0.0f;
    if (vtx < YX) {
        o.x = base[vtx];
        o.y = base[YX + vtx];
        o.z = base[2 * YX + vtx];
    } else if (vtx == YX) {
        float s[3];
        #pragma unroll
        for (int c = 0; c < 3; c++) {
            s[c] = 0.0f;
            #pragma unroll
            for (int i = 0; i < 5; i++) s[c] += base[c * YX + (i * BH) * XDIM];
            s[c] *= 0.2f;
        }
        o.x = s[0]; o.y = s[1]; o.z = s[2];
    } else {
        float s[3];
        #pragma unroll
        for (int c = 0; c < 3; c++) {
            s[c] = 0.0f;
            #pragma unroll
            for (int i = 1; i <= 5; i++)
                s[c] += base[c * YX + (i * BH - 1) * XDIM + (XDIM - 1)];
            s[c] *= 0.2f;
        }
        o.x = s[0]; o.y = s[1]; o.z = s[2];
    }
    g_v4[(size_t)b * NV + vtx] = o;
}

// ---------------------------------------------------------------------------
// K2: collect per-vertex opposite-edge pairs from faces (batch-independent).
// Face (f0,f1,f2): pair (f1,f2)->f0, (f2,f0)->f1, (f0,f1)->f2.
// Identity: summing full face normals around a closed ring telescopes to
// vn[v] = sum_i a_i x b_i over opposite-edge pairs.
// ---------------------------------------------------------------------------
__global__ void k_ring(const int* __restrict__ faces, int F) {
    int f = blockIdx.x * blockDim.x + threadIdx.x;
    if (f >= F) return;
    int a = faces[3 * f], b = faces[3 * f + 1], c = faces[3 * f + 2];
    int s;
    s = atomicAdd(&g_cnt[a], 1); g_ring[a * 6 + s] = make_int2(b, c);
    s = atomicAdd(&g_cnt[b], 1); g_ring[b * 6 + s] = make_int2(c, a);
    s = atomicAdd(&g_cnt[c], 1); g_ring[c * 6 + s] = make_int2(a, b);
}

// ---------------------------------------------------------------------------
// K2b: chain pairs into cyclic ring order (succ(a)=b), then ROTATE the ring
// so the minimal-index neighbor comes first. Rotation is free (both the cross
// sum and the neighbor sum are cyclic-invariant) and makes slot j hold the
// same "kind" of neighbor across consecutive vertices -> warp-coalesced
// gathers in k_loss. For deg-5, slot 5 duplicates slot 0 so its wrap cross
// term vanishes. cnt doubles as the vertex degree.
// ---------------------------------------------------------------------------
__global__ void k_order() {
    int v = blockIdx.x * blockDim.x + threadIdx.x;
    if (v >= NV) return;
    int cnt = g_cnt[v];
    int2 pr[6];
    #pragma unroll
    for (int i = 0; i < 6; i++)
        pr[i] = (i < cnt) ? g_ring[v * 6 + i] : make_int2(-1, -1);
    int ord[6];
    ord[0] = pr[0].x;
    int cur = pr[0].y;
    #pragma unroll
    for (int k = 1; k < 6; k++) {
        ord[k] = cur;
        int nxt = cur;
        #pragma unroll
        for (int i = 0; i < 6; i++)
            if (pr[i].x == cur) nxt = pr[i].y;
        cur = nxt;
    }
    // rotate ring (length cnt) to start at the minimal neighbor index
    int best = 0;
    #pragma unroll
    for (int i = 1; i < 6; i++)
        if (i < cnt && ord[i] < ord[best]) best = i;
    int rot[6];
    #pragma unroll
    for (int k = 0; k < 6; k++) {
        int idx = best + k;
        if (idx >= cnt) idx -= cnt;          // (best+k) mod cnt, cnt in {5,6}
        if (idx >= cnt) idx -= cnt;
        rot[k] = ord[idx];
    }
    if (cnt == 5) rot[5] = rot[0];
    g_nbr[2 * v]     = make_int4(rot[0], rot[1], rot[2], rot[3]);
    g_nbr[2 * v + 1] = make_int4(rot[4], rot[5], cnt, 0);
}

// ---------------------------------------------------------------------------
// K3: fused loss. One thread per vertex, BPT batches per thread.
// 7 LDG.128 gathers (warp-coherent after ring rotation) + 9 streamed target
// reads per vertex-batch. Last block (ticket) writes the final scalar.
// ---------------------------------------------------------------------------
__global__ void __launch_bounds__(128) k_loss(const float* __restrict__ target,
                                             float* __restrict__ out,
                                             unsigned int nblocks) {
    int vtx = blockIdx.x * blockDim.x + threadIdx.x;
    float local = 0.0f;
    if (vtx < NV) {
        int4 lo = g_nbr[2 * vtx];
        int4 hi = g_nbr[2 * vtx + 1];
        int n[6] = {lo.x, lo.y, lo.z, lo.w, hi.x, hi.y};
        int cnt  = hi.z;
        float invd = 1.0f / (float)cnt;
        const float inv3 = 1.0f / 3.0f;

        #pragma unroll
        for (int bb = 0; bb < BPT; bb++) {
            int b = blockIdx.y * BPT + bb;
            const float4* vb = g_v4 + (size_t)b * NV;

            float4 p[6];
            #pragma unroll
            for (int i = 0; i < 6; i++) p[i] = __ldg(vb + n[i]);
            float4 pv = __ldg(vb + vtx);

            // ring-ordered cross sum: vn = sum_j p_j x p_{(j+1)%6}
            float nx = 0.f, ny = 0.f, nz = 0.f;
            #pragma unroll
            for (int j = 0; j < 6; j++) {
                const float4 a = p[j];
                const float4 c = p[(j + 1) % 6];
                nx += a.y * c.z - a.z * c.y;
                ny += a.z * c.x - a.x * c.z;
                nz += a.x * c.y - a.y * c.x;
            }
            // neighbor sum (subtract the duplicated n0 if deg==5)
            float sx = 0.f, sy = 0.f, sz = 0.f;
            #pragma unroll
            for (int j = 0; j < 6; j++) { sx += p[j].x; sy += p[j].y; sz += p[j].z; }
            if (cnt == 5) { sx -= p[0].x; sy -= p[0].y; sz -= p[0].z; }

            const float* t = target + (size_t)b * 9 * NV + vtx;
            // position loss (streamed target reads: evict-first)
            float dx = pv.x - __ldcs(t);
            float dy = pv.y - __ldcs(t + (size_t)NV);
            float dz = pv.z - __ldcs(t + 2 * (size_t)NV);
            float lpos = dx * dx + dy * dy + dz * dz;
            // normal cosine loss
            float nn  = sqrtf(nx * nx + ny * ny + nz * nz);
            float inv = 1.0f / fmaxf(nn, 1e-12f);
            float ux = nx * inv, uy = ny * inv, uz = nz * inv;
            float un = sqrtf(ux * ux + uy * uy + uz * uz);
            float tx = __ldcs(t + 3 * (size_t)NV);
            float ty = __ldcs(t + 4 * (size_t)NV);
            float tz = __ldcs(t + 5 * (size_t)NV);
            float tn = sqrtf(tx * tx + ty * ty + tz * tz);
            float cosv = (ux * tx + uy * ty + uz * tz) / fmaxf(un * tn, 1e-8f);
            // Laplacian loss
            float dlx = (pv.x - sx * invd) - __ldcs(t + 6 * (size_t)NV);
            float dly = (pv.y - sy * invd) - __ldcs(t + 7 * (size_t)NV);
            float dlz = (pv.z - sz * invd) - __ldcs(t + 8 * (size_t)NV);
            float llap = dlx * dlx + dly * dly + dlz * dlz;

            local += (lpos + llap) * inv3 + (1.0f - cosv);
        }
    }

    // warp shuffle reduce, then cross-warp smem reduce, one atomic per block
    #pragma unroll
    for (int off = 16; off > 0; off >>= 1)
        local += __shfl_xor_sync(0xFFFFFFFFu, local, off);
    __shared__ float shw[4];
    int wid = threadIdx.x >> 5;
    if ((threadIdx.x & 31) == 0) shw[wid] = local;
    __syncthreads();
    if (threadIdx.x == 0) {
        float s = shw[0] + shw[1] + shw[2] + shw[3];
        atomicAdd(&g_acc, (double)s);
        __threadfence();
        unsigned int ticket = atomicAdd(&g_done, 1u);
        if (ticket == nblocks - 1u) {
            out[0] = (float)(g_acc / ((double)BATCH * (double)NV));
        }
    }
}

extern "C" void kernel_launch(void* const* d_in, const int* in_sizes, int n_in,
                              void* d_out, int out_size) {
    const float* inputs = (const float*)d_in[0];
    const float* target = (const float*)d_in[1];
    const int*   faces  = (const int*)  d_in[2];
    int F = in_sizes[2] / 3;

    dim3 blk256(256);
    k_build_v<<<dim3((YX + 2 + 255) / 256, BATCH), blk256>>>(inputs);
    k_ring   <<<(F + 255) / 256, blk256>>>(faces, F);
    k_order  <<<(NV + 255) / 256, blk256>>>();
    dim3 lgrid((NV + 127) / 128, BATCH / BPT);
    unsigned int nblocks = lgrid.x * lgrid.y;
    k_loss   <<<lgrid, 128>>>(target, (float*)d_out, nblocks);
}

// round 9
// speedup vs baseline: 1.2317x; 1.0392x over previous
#include <cuda_runtime.h>

// Problem constants (SUBDIVISIONS=7, BATCH=16)
#define BATCH 16
#define YDIM  640
#define XDIM  256
#define BH    128            // YDIM/5
#define YX    (YDIM*XDIM)    // 163840
#define NV    (YX + 2)       // 163842 vertices
#define BPT   4              // batches per thread in the fused loss kernel

// Scratch (static __device__ — no allocation allowed)
__device__ float4 g_v4[BATCH * NV];   // padded xyz_ per batch (~42 MB)
__device__ int    g_cnt[NV];          // per-vertex ring fill counters
__device__ int2   g_ring[NV * 6];     // per-vertex opposite-edge pairs (a,b)
__device__ int4   g_nbr[NV * 2];      // ring-ordered neighbors: [n0..n5, cnt, _]
__device__ double g_acc;              // fused loss accumulator
__device__ unsigned int g_done;       // ticket counter for fused finalization

// ---------------------------------------------------------------------------
// K0: zero counters + accumulators (head of the side-stream topology chain)
// ---------------------------------------------------------------------------
__global__ void k_zero() {
    int i = blockIdx.x * blockDim.x + threadIdx.x;
    if (i < NV) g_cnt[i] = 0;
    if (i == 0) { g_acc = 0.0; g_done = 0u; }
}

// ---------------------------------------------------------------------------
// K1: build v = [grid verts ; top pole ; bottom pole] as float4 (w unused).
// inputs layout: (B, 3, Y, X) row-major
// ---------------------------------------------------------------------------
__global__ void k_build_v(const float* __restrict__ inp) {
    int vtx = blockIdx.x * blockDim.x + threadIdx.x;
    int b   = blockIdx.y;
    if (vtx > YX + 1) return;
    const float* base = inp + (size_t)b * 3 * YX;
    float4 o;
    o.w = 0.0f;
    if (vtx < YX) {
        o.x = base[vtx];
        o.y = base[YX + vtx];
        o.z = base[2 * YX + vtx];
    } else if (vtx == YX) {
        float s[3];
        #pragma unroll
        for (int c = 0; c < 3; c++) {
            s[c] = 0.0f;
            #pragma unroll
            for (int i = 0; i < 5; i++) s[c] += base[c * YX + (i * BH) * XDIM];
            s[c] *= 0.2f;
        }
        o.x = s[0]; o.y = s[1]; o.z = s[2];
    } else {
        float s[3];
        #pragma unroll
        for (int c = 0; c < 3; c++) {
            s[c] = 0.0f;
            #pragma unroll
            for (int i = 1; i <= 5; i++)
                s[c] += base[c * YX + (i * BH - 1) * XDIM + (XDIM - 1)];
            s[c] *= 0.2f;
        }
        o.x = s[0]; o.y = s[1]; o.z = s[2];
    }
    g_v4[(size_t)b * NV + vtx] = o;
}

// ---------------------------------------------------------------------------
// K2: collect per-vertex opposite-edge pairs from faces (batch-independent).
// Face (f0,f1,f2): pair (f1,f2)->f0, (f2,f0)->f1, (f0,f1)->f2.
// Identity: summing full face normals around a closed ring telescopes to
// vn[v] = sum_i a_i x b_i over opposite-edge pairs.
// ---------------------------------------------------------------------------
__global__ void k_ring(const int* __restrict__ faces, int F) {
    int f = blockIdx.x * blockDim.x + threadIdx.x;
    if (f >= F) return;
    int a = faces[3 * f], b = faces[3 * f + 1], c = faces[3 * f + 2];
    int s;
    s = atomicAdd(&g_cnt[a], 1); g_ring[a * 6 + s] = make_int2(b, c);
    s = atomicAdd(&g_cnt[b], 1); g_ring[b * 6 + s] = make_int2(c, a);
    s = atomicAdd(&g_cnt[c], 1); g_ring[c * 6 + s] = make_int2(a, b);
}

// ---------------------------------------------------------------------------
// K2b: chain pairs into cyclic ring order (succ(a)=b), then ROTATE the ring
// so the minimal-index neighbor comes first (cyclic-invariant, improves
// warp gather coalescing in k_loss). For deg-5, slot 5 duplicates slot 0 so
// its wrap cross term vanishes. cnt doubles as the vertex degree.
// ---------------------------------------------------------------------------
__global__ void k_order() {
    int v = blockIdx.x * blockDim.x + threadIdx.x;
    if (v >= NV) return;
    int cnt = g_cnt[v];
    int2 pr[6];
    #pragma unroll
    for (int i = 0; i < 6; i++)
        pr[i] = (i < cnt) ? g_ring[v * 6 + i] : make_int2(-1, -1);
    int ord[6];
    ord[0] = pr[0].x;
    int cur = pr[0].y;
    #pragma unroll
    for (int k = 1; k < 6; k++) {
        ord[k] = cur;
        int nxt = cur;
        #pragma unroll
        for (int i = 0; i < 6; i++)
            if (pr[i].x == cur) nxt = pr[i].y;
        cur = nxt;
    }
    // rotate ring (length cnt) to start at the minimal neighbor index
    int best = 0;
    #pragma unroll
    for (int i = 1; i < 6; i++)
        if (i < cnt && ord[i] < ord[best]) best = i;
    int rot[6];
    #pragma unroll
    for (int k = 0; k < 6; k++) {
        int idx = best + k;
        if (idx >= cnt) idx -= cnt;          // (best+k) mod cnt, cnt in {5,6}
        if (idx >= cnt) idx -= cnt;
        rot[k] = ord[idx];
    }
    if (cnt == 5) rot[5] = rot[0];
    g_nbr[2 * v]     = make_int4(rot[0], rot[1], rot[2], rot[3]);
    g_nbr[2 * v + 1] = make_int4(rot[4], rot[5], cnt, 0);
}

// ---------------------------------------------------------------------------
// K3: fused loss (identical to the 82.4us round). One thread per vertex,
// BPT batches per thread. 7 LDG.128 gathers + 9 streamed target reads per
// vertex-batch. Last block (ticket) writes the final scalar.
// ---------------------------------------------------------------------------
__global__ void __launch_bounds__(128) k_loss(const float* __restrict__ target,
                                             float* __restrict__ out,
                                             unsigned int nblocks) {
    int vtx = blockIdx.x * blockDim.x + threadIdx.x;
    float local = 0.0f;
    if (vtx < NV) {
        int4 lo = g_nbr[2 * vtx];
        int4 hi = g_nbr[2 * vtx + 1];
        int n[6] = {lo.x, lo.y, lo.z, lo.w, hi.x, hi.y};
        int cnt  = hi.z;
        float invd = 1.0f / (float)cnt;
        const float inv3 = 1.0f / 3.0f;

        #pragma unroll
        for (int bb = 0; bb < BPT; bb++) {
            int b = blockIdx.y * BPT + bb;
            const float4* vb = g_v4 + (size_t)b * NV;

            float4 p[6];
            #pragma unroll
            for (int i = 0; i < 6; i++) p[i] = __ldg(vb + n[i]);
            float4 pv = __ldg(vb + vtx);

            // ring-ordered cross sum: vn = sum_j p_j x p_{(j+1)%6}
            float nx = 0.f, ny = 0.f, nz = 0.f;
            #pragma unroll
            for (int j = 0; j < 6; j++) {
                const float4 a = p[j];
                const float4 c = p[(j + 1) % 6];
                nx += a.y * c.z - a.z * c.y;
                ny += a.z * c.x - a.x * c.z;
                nz += a.x * c.y - a.y * c.x;
            }
            // neighbor sum (subtract the duplicated n0 if deg==5)
            float sx = 0.f, sy = 0.f, sz = 0.f;
            #pragma unroll
            for (int j = 0; j < 6; j++) { sx += p[j].x; sy += p[j].y; sz += p[j].z; }
            if (cnt == 5) { sx -= p[0].x; sy -= p[0].y; sz -= p[0].z; }

            const float* t = target + (size_t)b * 9 * NV + vtx;
            // position loss (streamed target reads: evict-first)
            float dx = pv.x - __ldcs(t);
            float dy = pv.y - __ldcs(t + (size_t)NV);
            float dz = pv.z - __ldcs(t + 2 * (size_t)NV);
            float lpos = dx * dx + dy * dy + dz * dz;
            // normal cosine loss
            float nn  = sqrtf(nx * nx + ny * ny + nz * nz);
            float inv = 1.0f / fmaxf(nn, 1e-12f);
            float ux = nx * inv, uy = ny * inv, uz = nz * inv;
            float un = sqrtf(ux * ux + uy * uy + uz * uz);
            float tx = __ldcs(t + 3 * (size_t)NV);
            float ty = __ldcs(t + 4 * (size_t)NV);
            float tz = __ldcs(t + 5 * (size_t)NV);
            float tn = sqrtf(tx * tx + ty * ty + tz * tz);
            float cosv = (ux * tx + uy * ty + uz * tz) / fmaxf(un * tn, 1e-8f);
            // Laplacian loss
            float dlx = (pv.x - sx * invd) - __ldcs(t + 6 * (size_t)NV);
            float dly = (pv.y - sy * invd) - __ldcs(t + 7 * (size_t)NV);
            float dlz = (pv.z - sz * invd) - __ldcs(t + 8 * (size_t)NV);
            float llap = dlx * dlx + dly * dly + dlz * dlz;

            local += (lpos + llap) * inv3 + (1.0f - cosv);
        }
    }

    // warp shuffle reduce, then cross-warp smem reduce, one atomic per block
    #pragma unroll
    for (int off = 16; off > 0; off >>= 1)
        local += __shfl_xor_sync(0xFFFFFFFFu, local, off);
    __shared__ float shw[4];
    int wid = threadIdx.x >> 5;
    if ((threadIdx.x & 31) == 0) shw[wid] = local;
    __syncthreads();
    if (threadIdx.x == 0) {
        float s = shw[0] + shw[1] + shw[2] + shw[3];
        atomicAdd(&g_acc, (double)s);
        __threadfence();
        unsigned int ticket = atomicAdd(&g_done, 1u);
        if (ticket == nblocks - 1u) {
            out[0] = (float)(g_acc / ((double)BATCH * (double)NV));
        }
    }
}

extern "C" void kernel_launch(void* const* d_in, const int* in_sizes, int n_in,
                              void* d_out, int out_size) {
    const float* inputs = (const float*)d_in[0];
    const float* target = (const float*)d_in[1];
    const int*   faces  = (const int*)  d_in[2];
    int F = in_sizes[2] / 3;

    // Side stream + events for fork-join overlap: the topology chain
    // (zero -> ring -> order) is data-independent of k_build_v, and the two
    // stress different resources (atomics/latency vs bandwidth). Created once
    // on the eager correctness call; the captured graph reuses the same
    // fork/join dependency structure.
    static cudaStream_t s_side = nullptr;
    static cudaEvent_t  s_fork = nullptr, s_join = nullptr;
    if (s_side == nullptr) {
        cudaStreamCreateWithFlags(&s_side, cudaStreamNonBlocking);
        cudaEventCreateWithFlags(&s_fork, cudaEventDisableTiming);
        cudaEventCreateWithFlags(&s_join, cudaEventDisableTiming);
    }
    cudaStream_t main_s = 0;

    dim3 blk256(256);

    // fork
    cudaEventRecord(s_fork, main_s);
    cudaStreamWaitEvent(s_side, s_fork, 0);

    // side stream: topology chain
    k_zero <<<(NV + 255) / 256, blk256, 0, s_side>>>();
    k_ring <<<(F + 255) / 256, blk256, 0, s_side>>>(faces, F);
    k_order<<<(NV + 255) / 256, blk256, 0, s_side>>>();
    cudaEventRecord(s_join, s_side);

    // main stream: vertex build, concurrent with the side chain
    k_build_v<<<dim3((YX + 2 + 255) / 256, BATCH), blk256, 0, main_s>>>(inputs);

    // join, then fused loss (identical shape to the 82.4us best)
    cudaStreamWaitEvent(main_s, s_join, 0);
    dim3 lgrid((NV + 127) / 128, BATCH / BPT);
    unsigned int nblocks = lgrid.x * lgrid.y;
    k_loss<<<lgrid, 128, 0, main_s>>>(target, (float*)d_out, nblocks);
}